// round 9
// baseline (speedup 1.0000x reference)
#include <cuda_runtime.h>
#include <cstdint>

#define NTHR  512
#define NGRID 148
#define MT    64          // edges per tile
#define FDIM  64
#define HID   128

// ---- smem layout (float offsets), all dense ----
#define S_A    0            // 64 x 128 A tile, XOR-swizzled, reused as h
#define S_W1X  8192         // [ws8][ks16][nt2][lane32][2]  = 16384
#define S_W1P  24576        // same
#define S_W2X  40960        // [nb4][ks16][nt2][lane32][2]  = 8192
#define S_B1X  49152        // 128
#define S_B1P  49280
#define S_W1XL 49408        // dist^2 row of W1x
#define S_W1PL 49536
#define S_W2P  49664        // 128
#define S_B2X  49792        // 64
#define S_DIST 49856        // 64
#define S_REL  49920        // 3 x 64
#define S_WACC 50112        // 8 x 64
#define S_COL  50624        // 64 (int)
#define S_TOT  50688
#define SMEM_BYTES (S_TOT * 4)

__device__ __forceinline__ uint32_t tf32(float f) {
    uint32_t u; asm("cvt.rna.tf32.f32 %0, %1;" : "=r"(u) : "f"(f)); return u;
}
static __device__ __forceinline__ float silu_f(float v) {
    return v * (1.0f / (1.0f + __expf(-v)));
}
__device__ __forceinline__ void mma8(float* c, const uint32_t* a, uint32_t b0, uint32_t b1) {
    asm volatile("mma.sync.aligned.m16n8k8.row.col.f32.tf32.tf32.f32 "
        "{%0,%1,%2,%3}, {%4,%5,%6,%7}, {%8,%9}, {%0,%1,%2,%3};"
        : "+f"(c[0]), "+f"(c[1]), "+f"(c[2]), "+f"(c[3])
        : "r"(a[0]), "r"(a[1]), "r"(a[2]), "r"(a[3]), "r"(b0), "r"(b1));
}

extern "C" __global__ void __launch_bounds__(NTHR, 1)
emp_mma_kernel(const float* __restrict__ x,
               const float* __restrict__ pos,
               const int* __restrict__ ei,
               const float* __restrict__ W1x, const float* __restrict__ b1x,
               const float* __restrict__ W2x, const float* __restrict__ b2x,
               const float* __restrict__ W1p, const float* __restrict__ b1p,
               const float* __restrict__ W2p, const float* __restrict__ b2p,
               float* __restrict__ out_x, float* __restrict__ out_pos,
               int E)
{
    extern __shared__ float sm[];
    uint32_t* smu = (uint32_t*)sm;
    int* scol = (int*)(sm + S_COL);

    const int t = threadIdx.x;
    const int lane = t & 31, wid = t >> 5;
    const int qr = lane >> 2, qc = lane & 3;

    // ---- one-time weight staging into MMA-native fragment layout ----
    // W1x/W1p: idx = ws*2048 + ks*128 + nt*64 + l*2 + r
    //   element: k = ks*8 + (l&3) + 4r ; n = ws*16 + nt*8 + (l>>2)
    for (int idx = t; idx < 16384; idx += NTHR) {
        int r = idx & 1, l = (idx >> 1) & 31, nt = (idx >> 6) & 1,
            ks = (idx >> 7) & 15, ws = (idx >> 11) & 7;
        int k = ks * 8 + (l & 3) + 4 * r;
        int n = ws * 16 + nt * 8 + (l >> 2);
        smu[S_W1X + idx] = tf32(W1x[k * HID + n]);
        smu[S_W1P + idx] = tf32(W1p[k * HID + n]);
    }
    // W2x: idx = nb*2048 + ks*128 + nt*64 + l*2 + r ; k = j index, n = f col
    for (int idx = t; idx < 8192; idx += NTHR) {
        int r = idx & 1, l = (idx >> 1) & 31, nt = (idx >> 6) & 1,
            ks = (idx >> 7) & 15, nb = (idx >> 11) & 3;
        int k = ks * 8 + (l & 3) + 4 * r;
        int f = nb * 16 + nt * 8 + (l >> 2);
        smu[S_W2X + idx] = tf32(W2x[k * FDIM + f]);
    }
    if (t < HID) {
        sm[S_B1X + t]  = b1x[t];
        sm[S_B1P + t]  = b1p[t];
        sm[S_W1XL + t] = W1x[HID * HID + t];
        sm[S_W1PL + t] = W1p[HID * HID + t];
        sm[S_W2P + t]  = W2p[t];
    }
    if (t < FDIM) sm[S_B2X + t] = b2x[t];
    const float b2p0 = __ldg(b2p);
    __syncthreads();

    const int ntiles = (E + MT - 1) / MT;
    const int e  = t & 63;          // local edge
    const int kb = t >> 6;          // k-block 0..7 (16 feats)
    const int esw = (e & 7) << 2;   // A-tile XOR swizzle for this row

    // ---- prefetch registers (current tile) ----
    float4 xv0, xv1, xv2, xv3;
    float pa0, pa1, pa2, pb0, pb1, pb2;
    int cur_c;

    // prologue: prefetch tile = blockIdx.x
    {
        int tile0 = blockIdx.x;
        int ge = tile0 * MT + e;
        int rn = -1, cn = -1;
        if (ge < E) { rn = ei[ge]; cn = ei[E + ge]; }
        cur_c = cn;
        int node = (kb < 4) ? rn : cn;
        if (node >= 0) {
            const float4* src = (const float4*)(x + (size_t)node * 64 + (kb & 3) * 16);
            xv0 = __ldg(src + 0); xv1 = __ldg(src + 1);
            xv2 = __ldg(src + 2); xv3 = __ldg(src + 3);
        } else {
            xv0 = xv1 = xv2 = xv3 = make_float4(0.f, 0.f, 0.f, 0.f);
        }
        pa0 = pa1 = pa2 = pb0 = pb1 = pb2 = 0.f;
        if (kb == 0 && rn >= 0) {
            pa0 = __ldg(pos + (size_t)rn * 3 + 0);
            pa1 = __ldg(pos + (size_t)rn * 3 + 1);
            pa2 = __ldg(pos + (size_t)rn * 3 + 2);
            pb0 = __ldg(pos + (size_t)cn * 3 + 0);
            pb1 = __ldg(pos + (size_t)cn * 3 + 1);
            pb2 = __ldg(pos + (size_t)cn * 3 + 2);
        }
    }

    for (int tile = blockIdx.x; tile < ntiles; tile += NGRID) {
        // ---------------- commit prefetched gather into A ----------------
        if (kb == 0) {
            float rx = pa0 - pb0, ry = pa1 - pb1, rz = pa2 - pb2;
            sm[S_REL + e] = rx; sm[S_REL + 64 + e] = ry; sm[S_REL + 128 + e] = rz;
            sm[S_DIST + e] = rx * rx + ry * ry + rz * rz;
            scol[e] = cur_c;
        }
        {
            uint32_t* base = smu + S_A + e * 128;
            const int k0 = kb * 16;
            *(uint4*)(base + ((k0 + 0)  ^ esw)) = make_uint4(tf32(xv0.x), tf32(xv0.y), tf32(xv0.z), tf32(xv0.w));
            *(uint4*)(base + ((k0 + 4)  ^ esw)) = make_uint4(tf32(xv1.x), tf32(xv1.y), tf32(xv1.z), tf32(xv1.w));
            *(uint4*)(base + ((k0 + 8)  ^ esw)) = make_uint4(tf32(xv2.x), tf32(xv2.y), tf32(xv2.z), tf32(xv2.w));
            *(uint4*)(base + ((k0 + 12) ^ esw)) = make_uint4(tf32(xv3.x), tf32(xv3.y), tf32(xv3.z), tf32(xv3.w));
        }
        __syncthreads();

        // prefetch next tile's edge indices (latency covered by GEMM1)
        int nrn = -1, ncn = -1;
        {
            int nt2 = tile + NGRID;
            if (nt2 < ntiles) {
                int ge2 = nt2 * MT + e;
                if (ge2 < E) { nrn = ei[ge2]; ncn = ei[E + ge2]; }
            }
        }

        // ---------------- GEMM1: combined @ {W1x, W1p} ----------------
        const int g  = wid >> 3;   // 0: phi_x (warps 0-7), 1: phi_p (8-15)
        const int ws = wid & 7;    // 16-col slice
        float acc[4][2][4];
        #pragma unroll
        for (int m = 0; m < 4; m++)
            #pragma unroll
            for (int n = 0; n < 2; n++)
                #pragma unroll
                for (int c = 0; c < 4; c++) acc[m][n][c] = 0.f;
        {
            const int wbase = (g ? S_W1P : S_W1X) + ws * 2048 + lane * 2;
            const int qsw = qr << 2;
            #pragma unroll
            for (int ks = 0; ks < 16; ks++) {
                const int k0 = ks * 8;
                const int col  = (k0 + qc) ^ qsw;
                const int col4 = col ^ 4;
                uint32_t a[4][4];
                #pragma unroll
                for (int m = 0; m < 4; m++) {
                    const uint32_t* p = smu + S_A + (m * 16 + qr) * 128;
                    a[m][0] = p[col]; a[m][1] = p[1024 + col];
                    a[m][2] = p[col4]; a[m][3] = p[1024 + col4];
                }
                uint2 bA = *(const uint2*)(smu + wbase + ks * 128);
                uint2 bB = *(const uint2*)(smu + wbase + ks * 128 + 64);
                #pragma unroll
                for (int m = 0; m < 4; m++) {
                    mma8(acc[m][0], a[m], bA.x, bA.y);
                    mma8(acc[m][1], a[m], bB.x, bB.y);
                }
            }
        }

        // prefetch next tile's x / pos into regs (latency covered by epi + GEMM2)
        {
            int node2 = (kb < 4) ? nrn : ncn;
            if (node2 >= 0) {
                const float4* src = (const float4*)(x + (size_t)node2 * 64 + (kb & 3) * 16);
                xv0 = __ldg(src + 0); xv1 = __ldg(src + 1);
                xv2 = __ldg(src + 2); xv3 = __ldg(src + 3);
            } else {
                xv0 = xv1 = xv2 = xv3 = make_float4(0.f, 0.f, 0.f, 0.f);
            }
            pa0 = pa1 = pa2 = pb0 = pb1 = pb2 = 0.f;
            if (kb == 0 && nrn >= 0) {
                pa0 = __ldg(pos + (size_t)nrn * 3 + 0);
                pa1 = __ldg(pos + (size_t)nrn * 3 + 1);
                pa2 = __ldg(pos + (size_t)nrn * 3 + 2);
                pb0 = __ldg(pos + (size_t)ncn * 3 + 0);
                pb1 = __ldg(pos + (size_t)ncn * 3 + 1);
                pb2 = __ldg(pos + (size_t)ncn * 3 + 2);
            }
        }
        __syncthreads();   // all A-tile reads done before h overwrites it

        // ---------------- epilogue 1 ----------------
        float dd0[4], dd1[4];
        #pragma unroll
        for (int m = 0; m < 4; m++) {
            dd0[m] = sm[S_DIST + m * 16 + qr];
            dd1[m] = sm[S_DIST + m * 16 + qr + 8];
        }
        if (g == 0) {
            // h = silu(acc + b1x + dist*w1xL) -> back into S_A (tf32, swizzled)
            #pragma unroll
            for (int n = 0; n < 2; n++) {
                const int j0 = ws * 16 + n * 8 + 2 * qc;
                const float bj0 = sm[S_B1X + j0],  bj1 = sm[S_B1X + j0 + 1];
                const float lj0 = sm[S_W1XL + j0], lj1 = sm[S_W1XL + j0 + 1];
                #pragma unroll
                for (int m = 0; m < 4; m++) {
                    const int r0 = m * 16 + qr;
                    float h00 = silu_f(acc[m][n][0] + bj0 + dd0[m] * lj0);
                    float h01 = silu_f(acc[m][n][1] + bj1 + dd0[m] * lj1);
                    float h10 = silu_f(acc[m][n][2] + bj0 + dd1[m] * lj0);
                    float h11 = silu_f(acc[m][n][3] + bj1 + dd1[m] * lj1);
                    const int sw = (qr << 2);
                    *(uint2*)(smu + S_A + r0 * 128 + (j0 ^ sw))         = make_uint2(tf32(h00), tf32(h01));
                    *(uint2*)(smu + S_A + (r0 + 8) * 128 + (j0 ^ sw))   = make_uint2(tf32(h10), tf32(h11));
                }
            }
        } else {
            // fold phi_p: wpart = sum_j silu(acc + b1p + dist*w1pL) * W2p[j]
            #pragma unroll
            for (int m = 0; m < 4; m++) {
                float pr0 = 0.f, pr1 = 0.f;
                #pragma unroll
                for (int n = 0; n < 2; n++) {
                    const int j0 = ws * 16 + n * 8 + 2 * qc;
                    const float bj0 = sm[S_B1P + j0],  bj1 = sm[S_B1P + j0 + 1];
                    const float lj0 = sm[S_W1PL + j0], lj1 = sm[S_W1PL + j0 + 1];
                    const float w0  = sm[S_W2P + j0],  w1  = sm[S_W2P + j0 + 1];
                    pr0 += silu_f(acc[m][n][0] + bj0 + dd0[m] * lj0) * w0
                         + silu_f(acc[m][n][1] + bj1 + dd0[m] * lj1) * w1;
                    pr1 += silu_f(acc[m][n][2] + bj0 + dd1[m] * lj0) * w0
                         + silu_f(acc[m][n][3] + bj1 + dd1[m] * lj1) * w1;
                }
                pr0 += __shfl_xor_sync(0xffffffff, pr0, 1);
                pr0 += __shfl_xor_sync(0xffffffff, pr0, 2);
                pr1 += __shfl_xor_sync(0xffffffff, pr1, 1);
                pr1 += __shfl_xor_sync(0xffffffff, pr1, 2);
                if (qc == 0) {
                    sm[S_WACC + ws * 64 + m * 16 + qr]     = pr0;
                    sm[S_WACC + ws * 64 + m * 16 + qr + 8] = pr1;
                }
            }
        }
        __syncthreads();

        // ---------------- pos scatter ----------------
        if (t < 64) {
            const int c = scol[t];
            if (c >= 0) {
                float w = b2p0;
                #pragma unroll
                for (int q = 0; q < 8; q++) w += sm[S_WACC + q * 64 + t];
                float px = w * sm[S_REL + t];
                float py = w * sm[S_REL + 64 + t];
                float pz = w * sm[S_REL + 128 + t];
                float* dp = out_pos + (size_t)c * 3;
                asm volatile("red.global.add.f32 [%0], %1;" :: "l"(dp + 0), "f"(px) : "memory");
                asm volatile("red.global.add.f32 [%0], %1;" :: "l"(dp + 1), "f"(py) : "memory");
                asm volatile("red.global.add.f32 [%0], %1;" :: "l"(dp + 2), "f"(pz) : "memory");
            }
        }

        // ---------------- GEMM2: h @ W2x ----------------
        {
            const int m2  = wid & 3;     // 16-edge m-tile
            const int nb2 = wid >> 2;    // 16-col n-slice
            float acc2[2][4];
            #pragma unroll
            for (int n = 0; n < 2; n++)
                #pragma unroll
                for (int c = 0; c < 4; c++) acc2[n][c] = 0.f;

            const int wbase = S_W2X + nb2 * 2048 + lane * 2;
            const int qsw = qr << 2;
            const uint32_t* Ap = smu + S_A + (m2 * 16 + qr) * 128;
            #pragma unroll
            for (int ks = 0; ks < 16; ks++) {
                const int k0 = ks * 8;
                const int col  = (k0 + qc) ^ qsw;
                const int col4 = col ^ 4;
                uint32_t a[4];
                a[0] = Ap[col]; a[1] = Ap[1024 + col];
                a[2] = Ap[col4]; a[3] = Ap[1024 + col4];
                uint2 bA = *(const uint2*)(smu + wbase + ks * 128);
                uint2 bB = *(const uint2*)(smu + wbase + ks * 128 + 64);
                mma8(acc2[0], a, bA.x, bA.y);
                mma8(acc2[1], a, bB.x, bB.y);
            }

            // epilogue 2: + b2x, vectorized scatter-add
            const int r0 = m2 * 16 + qr;
            const int c0 = scol[r0];
            const int c1 = scol[r0 + 8];
            #pragma unroll
            for (int n = 0; n < 2; n++) {
                const int f0 = nb2 * 16 + n * 8 + 2 * qc;
                const float b20 = sm[S_B2X + f0], b21 = sm[S_B2X + f0 + 1];
                if (c0 >= 0) {
                    float v0 = acc2[n][0] + b20, v1 = acc2[n][1] + b21;
                    asm volatile("red.global.add.v2.f32 [%0], {%1, %2};"
                                 :: "l"(out_x + (size_t)c0 * 64 + f0), "f"(v0), "f"(v1) : "memory");
                }
                if (c1 >= 0) {
                    float v0 = acc2[n][2] + b20, v1 = acc2[n][3] + b21;
                    asm volatile("red.global.add.v2.f32 [%0], {%1, %2};"
                                 :: "l"(out_x + (size_t)c1 * 64 + f0), "f"(v0), "f"(v1) : "memory");
                }
            }
        }
        cur_c = ncn;
        __syncthreads();   // protect S_A / S_WACC / S_COL before next commit
    }
}

extern "C" void kernel_launch(void* const* d_in, const int* in_sizes, int n_in,
                              void* d_out, int out_size) {
    const float* x   = (const float*)d_in[0];
    const float* pos = (const float*)d_in[1];
    const int*   ei  = (const int*)d_in[2];
    const float* W1x = (const float*)d_in[3];
    const float* b1x = (const float*)d_in[4];
    const float* W2x = (const float*)d_in[5];
    const float* b2x = (const float*)d_in[6];
    const float* W1p = (const float*)d_in[7];
    const float* b1p = (const float*)d_in[8];
    const float* W2p = (const float*)d_in[9];
    const float* b2p = (const float*)d_in[10];

    const int N = in_sizes[0] / FDIM;
    const int E = in_sizes[2] / 2;

    float* out     = (float*)d_out;
    float* out_x   = out;
    float* out_pos = out + (size_t)N * FDIM;

    cudaMemsetAsync(d_out, 0, (size_t)out_size * sizeof(float), 0);

    cudaFuncSetAttribute(emp_mma_kernel,
                         cudaFuncAttributeMaxDynamicSharedMemorySize, SMEM_BYTES);

    emp_mma_kernel<<<NGRID, NTHR, SMEM_BYTES>>>(
        x, pos, ei, W1x, b1x, W2x, b2x, W1p, b1p, W2p, b2p, out_x, out_pos, E);
}

// round 10
// speedup vs baseline: 1.4147x; 1.4147x over previous
#include <cuda_runtime.h>
#include <cstdint>

#define NTHR  512
#define NGRID 148
#define MT    64          // edges per tile
#define FDIM  64
#define HID   128

// ---- smem layout (float offsets), all dense ----
#define S_A    0            // 64 x 128 A tile, XOR-swizzled, reused as h
#define S_W1X  8192         // [ws8][ks16][nt2][lane32][2]  = 16384
#define S_W1P  24576        // same
#define S_W2X  40960        // [nb4][ks16][nt2][lane32][2]  = 8192
#define S_B1X  49152        // 128
#define S_B1P  49280
#define S_W1XL 49408        // dist^2 row of W1x
#define S_W1PL 49536
#define S_W2P  49664        // 128
#define S_B2X  49792        // 64
#define S_DIST 49856        // 64
#define S_REL  49920        // 3 x 64
#define S_WACC 50112        // 8 x 64
#define S_COL  50624        // 64 (int)
#define S_TOT  50688
#define SMEM_BYTES (S_TOT * 4)

__device__ __forceinline__ uint32_t tf32(float f) {
    uint32_t u; asm("cvt.rna.tf32.f32 %0, %1;" : "=r"(u) : "f"(f)); return u;
}
static __device__ __forceinline__ float silu_f(float v) {
    return v * (1.0f / (1.0f + __expf(-v)));
}
__device__ __forceinline__ void mma8(float* c, const uint32_t* a, uint32_t b0, uint32_t b1) {
    asm volatile("mma.sync.aligned.m16n8k8.row.col.f32.tf32.tf32.f32 "
        "{%0,%1,%2,%3}, {%4,%5,%6,%7}, {%8,%9}, {%0,%1,%2,%3};"
        : "+f"(c[0]), "+f"(c[1]), "+f"(c[2]), "+f"(c[3])
        : "r"(a[0]), "r"(a[1]), "r"(a[2]), "r"(a[3]), "r"(b0), "r"(b1));
}

extern "C" __global__ void __launch_bounds__(NTHR, 1)
emp_mma_kernel(const float* __restrict__ x,
               const float* __restrict__ pos,
               const int* __restrict__ ei,
               const float* __restrict__ W1x, const float* __restrict__ b1x,
               const float* __restrict__ W2x, const float* __restrict__ b2x,
               const float* __restrict__ W1p, const float* __restrict__ b1p,
               const float* __restrict__ W2p, const float* __restrict__ b2p,
               float* __restrict__ out_x, float* __restrict__ out_pos,
               int E)
{
    extern __shared__ float sm[];
    uint32_t* smu = (uint32_t*)sm;
    int* scol = (int*)(sm + S_COL);

    const int t = threadIdx.x;
    const int lane = t & 31, wid = t >> 5;
    const int qr = lane >> 2, qc = lane & 3;

    // ---- one-time weight staging into MMA-native fragment layout ----
    // W1x/W1p: idx = ws*2048 + ks*128 + nt*64 + l*2 + r
    //   element: k = ks*8 + (l&3) + 4r ; n = ws*16 + nt*8 + (l>>2)
    for (int idx = t; idx < 16384; idx += NTHR) {
        int r = idx & 1, l = (idx >> 1) & 31, nt = (idx >> 6) & 1,
            ks = (idx >> 7) & 15, ws = (idx >> 11) & 7;
        int k = ks * 8 + (l & 3) + 4 * r;
        int n = ws * 16 + nt * 8 + (l >> 2);
        smu[S_W1X + idx] = tf32(W1x[k * HID + n]);
        smu[S_W1P + idx] = tf32(W1p[k * HID + n]);
    }
    // W2x: idx = nb*2048 + ks*128 + nt*64 + l*2 + r ; k = j index, n = f col
    for (int idx = t; idx < 8192; idx += NTHR) {
        int r = idx & 1, l = (idx >> 1) & 31, nt = (idx >> 6) & 1,
            ks = (idx >> 7) & 15, nb = (idx >> 11) & 3;
        int k = ks * 8 + (l & 3) + 4 * r;
        int f = nb * 16 + nt * 8 + (l >> 2);
        smu[S_W2X + idx] = tf32(W2x[k * FDIM + f]);
    }
    if (t < HID) {
        sm[S_B1X + t]  = b1x[t];
        sm[S_B1P + t]  = b1p[t];
        sm[S_W1XL + t] = W1x[HID * HID + t];
        sm[S_W1PL + t] = W1p[HID * HID + t];
        sm[S_W2P + t]  = W2p[t];
    }
    if (t < FDIM) sm[S_B2X + t] = b2x[t];
    const float b2p0 = __ldg(b2p);
    __syncthreads();

    const int ntiles = (E + MT - 1) / MT;
    const int e  = t & 63;          // local edge
    const int kb = t >> 6;          // k-block 0..7 (16 feats)
    const int esw = (e & 7) << 2;   // A-tile XOR swizzle for this row

    for (int tile = blockIdx.x; tile < ntiles; tile += NGRID) {
        // ---------------- gather (in-loop, no register prefetch) ----------------
        const int ge = tile * MT + e;

        if (kb == 0) {
            if (ge < E) {
                int r = ei[ge], c = ei[E + ge];
                float rx = __ldg(pos + (size_t)r * 3 + 0) - __ldg(pos + (size_t)c * 3 + 0);
                float ry = __ldg(pos + (size_t)r * 3 + 1) - __ldg(pos + (size_t)c * 3 + 1);
                float rz = __ldg(pos + (size_t)r * 3 + 2) - __ldg(pos + (size_t)c * 3 + 2);
                sm[S_REL + e] = rx; sm[S_REL + 64 + e] = ry; sm[S_REL + 128 + e] = rz;
                sm[S_DIST + e] = rx * rx + ry * ry + rz * rz;
                scol[e] = c;
            } else {
                sm[S_REL + e] = 0.f; sm[S_REL + 64 + e] = 0.f; sm[S_REL + 128 + e] = 0.f;
                sm[S_DIST + e] = 0.f;
                scol[e] = -1;
            }
        }
        {
            uint32_t* base = smu + S_A + e * 128;
            const int k0 = kb * 16;
            if (ge < E) {
                const int node = ei[(kb < 4 ? 0 : E) + ge];
                const float4* src = (const float4*)(x + (size_t)node * 64 + (kb & 3) * 16);
                #pragma unroll
                for (int i = 0; i < 4; i++) {
                    float4 v = __ldg(src + i);
                    *(uint4*)(base + ((k0 + i * 4) ^ esw)) =
                        make_uint4(tf32(v.x), tf32(v.y), tf32(v.z), tf32(v.w));
                }
            } else {
                #pragma unroll
                for (int i = 0; i < 4; i++)
                    *(uint4*)(base + ((k0 + i * 4) ^ esw)) = make_uint4(0, 0, 0, 0);
            }
        }
        __syncthreads();

        // ---------------- GEMM1: combined @ {W1x, W1p} ----------------
        const int g  = wid >> 3;   // 0: phi_x (warps 0-7), 1: phi_p (8-15)
        const int ws = wid & 7;    // 16-col slice
        float acc[4][2][4];
        #pragma unroll
        for (int m = 0; m < 4; m++)
            #pragma unroll
            for (int n = 0; n < 2; n++)
                #pragma unroll
                for (int c = 0; c < 4; c++) acc[m][n][c] = 0.f;
        {
            const int wbase = (g ? S_W1P : S_W1X) + ws * 2048 + lane * 2;
            const int qsw = qr << 2;
            #pragma unroll
            for (int ks = 0; ks < 16; ks++) {
                const int k0 = ks * 8;
                const int col  = (k0 + qc) ^ qsw;
                const int col4 = col ^ 4;
                uint32_t a[4][4];
                #pragma unroll
                for (int m = 0; m < 4; m++) {
                    const uint32_t* p = smu + S_A + (m * 16 + qr) * 128;
                    a[m][0] = p[col]; a[m][1] = p[1024 + col];
                    a[m][2] = p[col4]; a[m][3] = p[1024 + col4];
                }
                uint2 bA = *(const uint2*)(smu + wbase + ks * 128);
                uint2 bB = *(const uint2*)(smu + wbase + ks * 128 + 64);
                #pragma unroll
                for (int m = 0; m < 4; m++) {
                    mma8(acc[m][0], a[m], bA.x, bA.y);
                    mma8(acc[m][1], a[m], bB.x, bB.y);
                }
            }
        }
        __syncthreads();   // all A-tile reads done before h overwrites it

        // ---------------- epilogue 1 ----------------
        float dd0[4], dd1[4];
        #pragma unroll
        for (int m = 0; m < 4; m++) {
            dd0[m] = sm[S_DIST + m * 16 + qr];
            dd1[m] = sm[S_DIST + m * 16 + qr + 8];
        }
        if (g == 0) {
            // h = silu(acc + b1x + dist*w1xL) -> back into S_A (tf32, swizzled)
            const int sw = qr << 2;
            #pragma unroll
            for (int n = 0; n < 2; n++) {
                const int j0 = ws * 16 + n * 8 + 2 * qc;
                const float bj0 = sm[S_B1X + j0],  bj1 = sm[S_B1X + j0 + 1];
                const float lj0 = sm[S_W1XL + j0], lj1 = sm[S_W1XL + j0 + 1];
                #pragma unroll
                for (int m = 0; m < 4; m++) {
                    const int r0 = m * 16 + qr;
                    float h00 = silu_f(acc[m][n][0] + bj0 + dd0[m] * lj0);
                    float h01 = silu_f(acc[m][n][1] + bj1 + dd0[m] * lj1);
                    float h10 = silu_f(acc[m][n][2] + bj0 + dd1[m] * lj0);
                    float h11 = silu_f(acc[m][n][3] + bj1 + dd1[m] * lj1);
                    *(uint2*)(smu + S_A + r0 * 128 + (j0 ^ sw))       = make_uint2(tf32(h00), tf32(h01));
                    *(uint2*)(smu + S_A + (r0 + 8) * 128 + (j0 ^ sw)) = make_uint2(tf32(h10), tf32(h11));
                }
            }
        } else {
            // fold phi_p: wpart = sum_j silu(acc + b1p + dist*w1pL) * W2p[j]
            #pragma unroll
            for (int m = 0; m < 4; m++) {
                float pr0 = 0.f, pr1 = 0.f;
                #pragma unroll
                for (int n = 0; n < 2; n++) {
                    const int j0 = ws * 16 + n * 8 + 2 * qc;
                    const float bj0 = sm[S_B1P + j0],  bj1 = sm[S_B1P + j0 + 1];
                    const float lj0 = sm[S_W1PL + j0], lj1 = sm[S_W1PL + j0 + 1];
                    const float w0  = sm[S_W2P + j0],  w1  = sm[S_W2P + j0 + 1];
                    pr0 += silu_f(acc[m][n][0] + bj0 + dd0[m] * lj0) * w0
                         + silu_f(acc[m][n][1] + bj1 + dd0[m] * lj1) * w1;
                    pr1 += silu_f(acc[m][n][2] + bj0 + dd1[m] * lj0) * w0
                         + silu_f(acc[m][n][3] + bj1 + dd1[m] * lj1) * w1;
                }
                pr0 += __shfl_xor_sync(0xffffffff, pr0, 1);
                pr0 += __shfl_xor_sync(0xffffffff, pr0, 2);
                pr1 += __shfl_xor_sync(0xffffffff, pr1, 1);
                pr1 += __shfl_xor_sync(0xffffffff, pr1, 2);
                if (qc == 0) {
                    sm[S_WACC + ws * 64 + m * 16 + qr]     = pr0;
                    sm[S_WACC + ws * 64 + m * 16 + qr + 8] = pr1;
                }
            }
        }
        __syncthreads();

        // ---------------- pos scatter ----------------
        if (t < 64) {
            const int c = scol[t];
            if (c >= 0) {
                float w = b2p0;
                #pragma unroll
                for (int q = 0; q < 8; q++) w += sm[S_WACC + q * 64 + t];
                float px = w * sm[S_REL + t];
                float py = w * sm[S_REL + 64 + t];
                float pz = w * sm[S_REL + 128 + t];
                float* dp = out_pos + (size_t)c * 3;
                asm volatile("red.global.add.f32 [%0], %1;" :: "l"(dp + 0), "f"(px) : "memory");
                asm volatile("red.global.add.f32 [%0], %1;" :: "l"(dp + 1), "f"(py) : "memory");
                asm volatile("red.global.add.f32 [%0], %1;" :: "l"(dp + 2), "f"(pz) : "memory");
            }
        }

        // ---------------- GEMM2: h @ W2x ----------------
        {
            const int m2  = wid & 3;     // 16-edge m-tile
            const int nb2 = wid >> 2;    // 16-col n-slice
            float acc2[2][4];
            #pragma unroll
            for (int n = 0; n < 2; n++)
                #pragma unroll
                for (int c = 0; c < 4; c++) acc2[n][c] = 0.f;

            const int wbase = S_W2X + nb2 * 2048 + lane * 2;
            const int qsw = qr << 2;
            const uint32_t* Ap = smu + S_A + (m2 * 16 + qr) * 128;
            #pragma unroll
            for (int ks = 0; ks < 16; ks++) {
                const int k0 = ks * 8;
                const int col  = (k0 + qc) ^ qsw;
                const int col4 = col ^ 4;
                uint32_t a[4];
                a[0] = Ap[col]; a[1] = Ap[1024 + col];
                a[2] = Ap[col4]; a[3] = Ap[1024 + col4];
                uint2 bA = *(const uint2*)(smu + wbase + ks * 128);
                uint2 bB = *(const uint2*)(smu + wbase + ks * 128 + 64);
                mma8(acc2[0], a, bA.x, bA.y);
                mma8(acc2[1], a, bB.x, bB.y);
            }

            // epilogue 2: + b2x, vectorized scatter-add
            const int r0 = m2 * 16 + qr;
            const int c0 = scol[r0];
            const int c1 = scol[r0 + 8];
            #pragma unroll
            for (int n = 0; n < 2; n++) {
                const int f0 = nb2 * 16 + n * 8 + 2 * qc;
                const float b20 = sm[S_B2X + f0], b21 = sm[S_B2X + f0 + 1];
                if (c0 >= 0) {
                    float v0 = acc2[n][0] + b20, v1 = acc2[n][1] + b21;
                    asm volatile("red.global.add.v2.f32 [%0], {%1, %2};"
                                 :: "l"(out_x + (size_t)c0 * 64 + f0), "f"(v0), "f"(v1) : "memory");
                }
                if (c1 >= 0) {
                    float v0 = acc2[n][2] + b20, v1 = acc2[n][3] + b21;
                    asm volatile("red.global.add.v2.f32 [%0], {%1, %2};"
                                 :: "l"(out_x + (size_t)c1 * 64 + f0), "f"(v0), "f"(v1) : "memory");
                }
            }
        }
        __syncthreads();   // protect S_A / S_WACC / S_COL before next tile's gather
    }
}

extern "C" void kernel_launch(void* const* d_in, const int* in_sizes, int n_in,
                              void* d_out, int out_size) {
    const float* x   = (const float*)d_in[0];
    const float* pos = (const float*)d_in[1];
    const int*   ei  = (const int*)d_in[2];
    const float* W1x = (const float*)d_in[3];
    const float* b1x = (const float*)d_in[4];
    const float* W2x = (const float*)d_in[5];
    const float* b2x = (const float*)d_in[6];
    const float* W1p = (const float*)d_in[7];
    const float* b1p = (const float*)d_in[8];
    const float* W2p = (const float*)d_in[9];
    const float* b2p = (const float*)d_in[10];

    const int N = in_sizes[0] / FDIM;
    const int E = in_sizes[2] / 2;

    float* out     = (float*)d_out;
    float* out_x   = out;
    float* out_pos = out + (size_t)N * FDIM;

    cudaMemsetAsync(d_out, 0, (size_t)out_size * sizeof(float), 0);

    cudaFuncSetAttribute(emp_mma_kernel,
                         cudaFuncAttributeMaxDynamicSharedMemorySize, SMEM_BYTES);

    emp_mma_kernel<<<NGRID, NTHR, SMEM_BYTES>>>(
        x, pos, ei, W1x, b1x, W2x, b2x, W1p, b1p, W2p, b2p, out_x, out_pos, E);
}

// round 12
// speedup vs baseline: 1.4329x; 1.0129x over previous
#include <cuda_runtime.h>
#include <cstdint>

#define NTHR  512
#define NGRID 148
#define MT    64          // edges per tile
#define FDIM  64
#define HID   128

// ---- smem layout (float offsets), all dense ----
#define S_A    0            // 64 x 128 A tile, XOR-swizzled, reused as h
#define S_W1C  8192         // combined W1x/W1p frags: [ws4][ks16][part4][lane32][4] = 32768
#define S_W2X  40960        // [nb4][ks16][lane32][4] = 8192
#define S_B1X  49152        // 128
#define S_B1P  49280
#define S_W1XL 49408        // dist^2 row of W1x
#define S_W1PL 49536
#define S_W2P  49664        // 128
#define S_B2X  49792        // 64
#define S_DIST 49856        // 64
#define S_REL  49920        // 3 x 64
#define S_WACC 50112        // 4 x 64
#define S_COL  50368        // 64 (int)
#define S_TOT  50432
#define SMEM_BYTES (S_TOT * 4)

__device__ __forceinline__ uint32_t tf32(float f) {
    uint32_t u; asm("cvt.rna.tf32.f32 %0, %1;" : "=r"(u) : "f"(f)); return u;
}
static __device__ __forceinline__ float silu_f(float v) {
    return v * (1.0f / (1.0f + __expf(-v)));
}
__device__ __forceinline__ void mma8(float* c, const uint32_t* a, uint32_t b0, uint32_t b1) {
    asm volatile("mma.sync.aligned.m16n8k8.row.col.f32.tf32.tf32.f32 "
        "{%0,%1,%2,%3}, {%4,%5,%6,%7}, {%8,%9}, {%0,%1,%2,%3};"
        : "+f"(c[0]), "+f"(c[1]), "+f"(c[2]), "+f"(c[3])
        : "r"(a[0]), "r"(a[1]), "r"(a[2]), "r"(a[3]), "r"(b0), "r"(b1));
}

extern "C" __global__ void __launch_bounds__(NTHR, 1)
emp_mma_kernel(const float* __restrict__ x,
               const float* __restrict__ pos,
               const int* __restrict__ ei,
               const float* __restrict__ W1x, const float* __restrict__ b1x,
               const float* __restrict__ W2x, const float* __restrict__ b2x,
               const float* __restrict__ W1p, const float* __restrict__ b1p,
               const float* __restrict__ W2p, const float* __restrict__ b2p,
               float* __restrict__ out_x, float* __restrict__ out_pos,
               int E)
{
    extern __shared__ float sm[];
    uint32_t* smu = (uint32_t*)sm;
    int* scol = (int*)(sm + S_COL);

    const int t = threadIdx.x;
    const int lane = t & 31, wid = t >> 5;
    const int qr = lane >> 2, qc = lane & 3;

    // ---- one-time weight staging ----
    // W1C: idx = ws*8192 + ks*512 + part*128 + lane*4 + q
    //   part: 0=x nt0/1, 1=x nt2/3, 2=p nt0/1, 3=p nt2/3
    //   q: (nt&1)*2 + r ; n = ws*32 + nt*8 + (lane>>2) ; k = ks*8 + (lane&3) + 4r
    for (int idx = t; idx < 32768; idx += NTHR) {
        int q = idx & 3, l = (idx >> 2) & 31, part = (idx >> 7) & 3,
            ks = (idx >> 9) & 15, ws = (idx >> 13) & 3;
        int mlp = part >> 1;
        int nt  = (part & 1) * 2 + (q >> 1);
        int r   = q & 1;
        int n = ws * 32 + nt * 8 + (l >> 2);
        int k = ks * 8 + (l & 3) + 4 * r;
        const float* W = mlp ? W1p : W1x;
        smu[S_W1C + idx] = tf32(W[k * HID + n]);
    }
    // W2X: idx = nb*2048 + ks*128 + lane*4 + q ; f = nb*16 + (q>>1)*8 + (lane>>2)
    for (int idx = t; idx < 8192; idx += NTHR) {
        int q = idx & 3, l = (idx >> 2) & 31, ks = (idx >> 7) & 15, nb = (idx >> 11) & 3;
        int nt = q >> 1, r = q & 1;
        int f = nb * 16 + nt * 8 + (l >> 2);
        int k = ks * 8 + (l & 3) + 4 * r;
        smu[S_W2X + idx] = tf32(W2x[k * FDIM + f]);
    }
    if (t < HID) {
        sm[S_B1X + t]  = b1x[t];
        sm[S_B1P + t]  = b1p[t];
        sm[S_W1XL + t] = W1x[HID * HID + t];
        sm[S_W1PL + t] = W1p[HID * HID + t];
        sm[S_W2P + t]  = W2p[t];
    }
    if (t < FDIM) sm[S_B2X + t] = b2x[t];
    const float b2p0 = __ldg(b2p);
    __syncthreads();

    const int ntiles = (E + MT - 1) / MT;
    const int e  = t & 63;          // local edge
    const int kb = t >> 6;          // k-block 0..7 (16 feats)
    const int esw = (e & 7) << 2;   // A-tile XOR swizzle for this row

    for (int tile = blockIdx.x; tile < ntiles; tile += NGRID) {
        // ---------------- gather ----------------
        const int ge = tile * MT + e;

        if (kb == 0) {
            if (ge < E) {
                int r = ei[ge], c = ei[E + ge];
                float rx = __ldg(pos + (size_t)r * 3 + 0) - __ldg(pos + (size_t)c * 3 + 0);
                float ry = __ldg(pos + (size_t)r * 3 + 1) - __ldg(pos + (size_t)c * 3 + 1);
                float rz = __ldg(pos + (size_t)r * 3 + 2) - __ldg(pos + (size_t)c * 3 + 2);
                sm[S_REL + e] = rx; sm[S_REL + 64 + e] = ry; sm[S_REL + 128 + e] = rz;
                sm[S_DIST + e] = rx * rx + ry * ry + rz * rz;
                scol[e] = c;
            } else {
                sm[S_REL + e] = 0.f; sm[S_REL + 64 + e] = 0.f; sm[S_REL + 128 + e] = 0.f;
                sm[S_DIST + e] = 0.f;
                scol[e] = -1;
            }
        }
        {
            uint32_t* base = smu + S_A + e * 128;
            const int k0 = kb * 16;
            if (ge < E) {
                const int node = ei[(kb < 4 ? 0 : E) + ge];
                const float4* src = (const float4*)(x + (size_t)node * 64 + (kb & 3) * 16);
                #pragma unroll
                for (int i = 0; i < 4; i++) {
                    float4 v = __ldg(src + i);
                    *(uint4*)(base + ((k0 + i * 4) ^ esw)) =
                        make_uint4(tf32(v.x), tf32(v.y), tf32(v.z), tf32(v.w));
                }
            } else {
                #pragma unroll
                for (int i = 0; i < 4; i++)
                    *(uint4*)(base + ((k0 + i * 4) ^ esw)) = make_uint4(0, 0, 0, 0);
            }
        }
        __syncthreads();

        // ---------------- GEMM1: warp = (m-group, n-slice), both MLPs ----------------
        const int mg = wid & 3;    // 16-edge m-group
        const int ws = wid >> 2;   // 32-col n-slice (of both W1x and W1p)
        float acc[8][4];           // n-tiles 0-3: phi_x, 4-7: phi_p
        #pragma unroll
        for (int n = 0; n < 8; n++)
            #pragma unroll
            for (int c = 0; c < 4; c++) acc[n][c] = 0.f;
        {
            const uint32_t* Ap = smu + S_A + (mg * 16 + qr) * 128;
            const int wbase = S_W1C + ws * 8192 + lane * 4;
            const int qsw = qr << 2;
            #pragma unroll
            for (int ks = 0; ks < 16; ks++) {
                const int col  = (ks * 8 + qc) ^ qsw;
                const int col4 = col ^ 4;
                uint32_t a[4];
                a[0] = Ap[col]; a[1] = Ap[1024 + col];
                a[2] = Ap[col4]; a[3] = Ap[1024 + col4];
                uint4 b0 = *(const uint4*)(smu + wbase + ks * 512);
                uint4 b1 = *(const uint4*)(smu + wbase + ks * 512 + 128);
                uint4 b2 = *(const uint4*)(smu + wbase + ks * 512 + 256);
                uint4 b3 = *(const uint4*)(smu + wbase + ks * 512 + 384);
                mma8(acc[0], a, b0.x, b0.y); mma8(acc[1], a, b0.z, b0.w);
                mma8(acc[2], a, b1.x, b1.y); mma8(acc[3], a, b1.z, b1.w);
                mma8(acc[4], a, b2.x, b2.y); mma8(acc[5], a, b2.z, b2.w);
                mma8(acc[6], a, b3.x, b3.y); mma8(acc[7], a, b3.z, b3.w);
            }
        }
        __syncthreads();   // all A-tile reads done before h overwrites it

        // ---------------- epilogue 1 (each warp: h slice + phi_p fold) ----------------
        {
            const float dd0 = sm[S_DIST + mg * 16 + qr];
            const float dd1 = sm[S_DIST + mg * 16 + qr + 8];
            const int sw = qr << 2;
            const int r0 = mg * 16 + qr;
            // phi_x: h = silu(acc + b1x + dist*w1xL) -> S_A (tf32, swizzled)
            #pragma unroll
            for (int nt = 0; nt < 4; nt++) {
                const int j0 = ws * 32 + nt * 8 + 2 * qc;
                const float bj0 = sm[S_B1X + j0],  bj1 = sm[S_B1X + j0 + 1];
                const float lj0 = sm[S_W1XL + j0], lj1 = sm[S_W1XL + j0 + 1];
                float h00 = silu_f(acc[nt][0] + bj0 + dd0 * lj0);
                float h01 = silu_f(acc[nt][1] + bj1 + dd0 * lj1);
                float h10 = silu_f(acc[nt][2] + bj0 + dd1 * lj0);
                float h11 = silu_f(acc[nt][3] + bj1 + dd1 * lj1);
                *(uint2*)(smu + S_A + r0 * 128 + (j0 ^ sw))       = make_uint2(tf32(h00), tf32(h01));
                *(uint2*)(smu + S_A + (r0 + 8) * 128 + (j0 ^ sw)) = make_uint2(tf32(h10), tf32(h11));
            }
            // phi_p: fold to per-edge partial over this 32-col slice
            float pr0 = 0.f, pr1 = 0.f;
            #pragma unroll
            for (int nt = 0; nt < 4; nt++) {
                const int j0 = ws * 32 + nt * 8 + 2 * qc;
                const float bj0 = sm[S_B1P + j0],  bj1 = sm[S_B1P + j0 + 1];
                const float lj0 = sm[S_W1PL + j0], lj1 = sm[S_W1PL + j0 + 1];
                const float w0  = sm[S_W2P + j0],  w1  = sm[S_W2P + j0 + 1];
                pr0 += silu_f(acc[4 + nt][0] + bj0 + dd0 * lj0) * w0
                     + silu_f(acc[4 + nt][1] + bj1 + dd0 * lj1) * w1;
                pr1 += silu_f(acc[4 + nt][2] + bj0 + dd1 * lj0) * w0
                     + silu_f(acc[4 + nt][3] + bj1 + dd1 * lj1) * w1;
            }
            pr0 += __shfl_xor_sync(0xffffffff, pr0, 1);
            pr0 += __shfl_xor_sync(0xffffffff, pr0, 2);
            pr1 += __shfl_xor_sync(0xffffffff, pr1, 1);
            pr1 += __shfl_xor_sync(0xffffffff, pr1, 2);
            if (qc == 0) {
                sm[S_WACC + ws * 64 + r0]     = pr0;
                sm[S_WACC + ws * 64 + r0 + 8] = pr1;
            }
        }
        __syncthreads();

        // ---------------- pos scatter ----------------
        if (t < 64) {
            const int c = scol[t];
            if (c >= 0) {
                float w = b2p0 + sm[S_WACC + t] + sm[S_WACC + 64 + t]
                               + sm[S_WACC + 128 + t] + sm[S_WACC + 192 + t];
                float px = w * sm[S_REL + t];
                float py = w * sm[S_REL + 64 + t];
                float pz = w * sm[S_REL + 128 + t];
                float* dp = out_pos + (size_t)c * 3;
                asm volatile("red.global.add.f32 [%0], %1;" :: "l"(dp + 0), "f"(px) : "memory");
                asm volatile("red.global.add.f32 [%0], %1;" :: "l"(dp + 1), "f"(py) : "memory");
                asm volatile("red.global.add.f32 [%0], %1;" :: "l"(dp + 2), "f"(pz) : "memory");
            }
        }

        // ---------------- GEMM2: h @ W2x ----------------
        {
            const int m2  = wid & 3;     // 16-edge m-tile
            const int nb2 = wid >> 2;    // 16-col n-slice
            float acc2[2][4];
            #pragma unroll
            for (int n = 0; n < 2; n++)
                #pragma unroll
                for (int c = 0; c < 4; c++) acc2[n][c] = 0.f;

            const int wbase = S_W2X + nb2 * 2048 + lane * 4;
            const int qsw = qr << 2;
            const uint32_t* Ap = smu + S_A + (m2 * 16 + qr) * 128;
            #pragma unroll
            for (int ks = 0; ks < 16; ks++) {
                const int col  = (ks * 8 + qc) ^ qsw;
                const int col4 = col ^ 4;
                uint32_t a[4];
                a[0] = Ap[col]; a[1] = Ap[1024 + col];
                a[2] = Ap[col4]; a[3] = Ap[1024 + col4];
                uint4 bb = *(const uint4*)(smu + wbase + ks * 128);
                mma8(acc2[0], a, bb.x, bb.y);
                mma8(acc2[1], a, bb.z, bb.w);
            }

            // epilogue 2: + b2x, vectorized scatter-add
            const int r0 = m2 * 16 + qr;
            const int c0 = scol[r0];
            const int c1 = scol[r0 + 8];
            #pragma unroll
            for (int n = 0; n < 2; n++) {
                const int f0 = nb2 * 16 + n * 8 + 2 * qc;
                const float b20 = sm[S_B2X + f0], b21 = sm[S_B2X + f0 + 1];
                if (c0 >= 0) {
                    float v0 = acc2[n][0] + b20, v1 = acc2[n][1] + b21;
                    asm volatile("red.global.add.v2.f32 [%0], {%1, %2};"
                                 :: "l"(out_x + (size_t)c0 * 64 + f0), "f"(v0), "f"(v1) : "memory");
                }
                if (c1 >= 0) {
                    float v0 = acc2[n][2] + b20, v1 = acc2[n][3] + b21;
                    asm volatile("red.global.add.v2.f32 [%0], {%1, %2};"
                                 :: "l"(out_x + (size_t)c1 * 64 + f0), "f"(v0), "f"(v1) : "memory");
                }
            }
        }
        __syncthreads();   // protect S_A / S_WACC / S_COL before next tile's gather
    }
}

extern "C" void kernel_launch(void* const* d_in, const int* in_sizes, int n_in,
                              void* d_out, int out_size) {
    const float* x   = (const float*)d_in[0];
    const float* pos = (const float*)d_in[1];
    const int*   ei  = (const int*)d_in[2];
    const float* W1x = (const float*)d_in[3];
    const float* b1x = (const float*)d_in[4];
    const float* W2x = (const float*)d_in[5];
    const float* b2x = (const float*)d_in[6];
    const float* W1p = (const float*)d_in[7];
    const float* b1p = (const float*)d_in[8];
    const float* W2p = (const float*)d_in[9];
    const float* b2p = (const float*)d_in[10];

    const int N = in_sizes[0] / FDIM;
    const int E = in_sizes[2] / 2;

    float* out     = (float*)d_out;
    float* out_x   = out;
    float* out_pos = out + (size_t)N * FDIM;

    cudaMemsetAsync(d_out, 0, (size_t)out_size * sizeof(float), 0);

    cudaFuncSetAttribute(emp_mma_kernel,
                         cudaFuncAttributeMaxDynamicSharedMemorySize, SMEM_BYTES);

    emp_mma_kernel<<<NGRID, NTHR, SMEM_BYTES>>>(
        x, pos, ei, W1x, b1x, W2x, b2x, W1p, b1p, W2p, b2p, out_x, out_pos, E);
}

// round 13
// speedup vs baseline: 1.9755x; 1.3787x over previous
#include <cuda_runtime.h>
#include <cuda_fp16.h>
#include <cstdint>

#define NTHR  512
#define NGRID 148
#define MT    64          // edges per tile
#define FDIM  64
#define HID   128

// ---- smem layout (uint32/float offsets), all dense ----
#define S_A    0            // 64 x 64 uint32 (half2 pairs), XOR-swizzled, reused as h
#define S_W1C  4096         // [ws4][ks8][grp4][lane32][4] = 16384 uint32 (W1x+W1p halves)
#define S_W2X  20480        // [nb4][ks8][lane32][4] = 4096 uint32
#define S_B1X  24576        // 128 fp32
#define S_B1P  24704
#define S_W1XL 24832        // dist^2 row of W1x
#define S_W1PL 24960
#define S_W2P  25088        // 128 fp32
#define S_B2X  25216        // 64
#define S_DIST 25280        // 64
#define S_REL  25344        // 3 x 64
#define S_WACC 25536        // 4 x 64
#define S_COL  25792        // 64 (int)
#define S_TOT  25856
#define SMEM_BYTES (S_TOT * 4)

__device__ __forceinline__ uint32_t f2h2(float lo, float hi) {
    __half2 h = __floats2half2_rn(lo, hi);
    return *(uint32_t*)&h;
}
static __device__ __forceinline__ float silu_f(float v) {
    return v * (1.0f / (1.0f + __expf(-v)));
}
__device__ __forceinline__ void mma16(float* c, const uint32_t* a, uint32_t b0, uint32_t b1) {
    asm volatile("mma.sync.aligned.m16n8k16.row.col.f32.f16.f16.f32 "
        "{%0,%1,%2,%3}, {%4,%5,%6,%7}, {%8,%9}, {%0,%1,%2,%3};"
        : "+f"(c[0]), "+f"(c[1]), "+f"(c[2]), "+f"(c[3])
        : "r"(a[0]), "r"(a[1]), "r"(a[2]), "r"(a[3]), "r"(b0), "r"(b1));
}

extern "C" __global__ void __launch_bounds__(NTHR, 1)
emp_mma_kernel(const float* __restrict__ x,
               const float* __restrict__ pos,
               const int* __restrict__ ei,
               const float* __restrict__ W1x, const float* __restrict__ b1x,
               const float* __restrict__ W2x, const float* __restrict__ b2x,
               const float* __restrict__ W1p, const float* __restrict__ b1p,
               const float* __restrict__ W2p, const float* __restrict__ b2p,
               float* __restrict__ out_x, float* __restrict__ out_pos,
               int E)
{
    extern __shared__ float sm[];
    uint32_t* smu = (uint32_t*)sm;
    int* scol = (int*)(sm + S_COL);

    const int t = threadIdx.x;
    const int lane = t & 31, wid = t >> 5;
    const int qr = lane >> 2, qc = lane & 3;

    // ---- one-time weight staging into m16n8k16 fragment layout (half2 packed) ----
    // W1C: idx = ws*4096 + ks*512 + grp*128 + lane*4 + q
    //   nt = grp*2 + (q>>1)  (0-3: W1x n-tiles, 4-7: W1p), r = q&1
    //   n = ws*32 + (nt&3)*8 + (lane>>2) ; pair = ks*8 + (lane&3) + 4r ; k = 2*pair
    for (int idx = t; idx < 16384; idx += NTHR) {
        int q = idx & 3, l = (idx >> 2) & 31, grp = (idx >> 7) & 3,
            ks = (idx >> 9) & 7, ws = (idx >> 12) & 3;
        int nt = grp * 2 + (q >> 1), r = q & 1;
        int n = ws * 32 + (nt & 3) * 8 + (l >> 2);
        int k = 2 * (ks * 8 + (l & 3) + 4 * r);
        const float* W = (nt >= 4) ? W1p : W1x;
        smu[S_W1C + idx] = f2h2(W[k * HID + n], W[(k + 1) * HID + n]);
    }
    // W2X: idx = nb*1024 + ks*128 + lane*4 + q ; nt = q>>1, r = q&1
    for (int idx = t; idx < 4096; idx += NTHR) {
        int q = idx & 3, l = (idx >> 2) & 31, ks = (idx >> 7) & 7, nb = (idx >> 10) & 3;
        int nt = q >> 1, r = q & 1;
        int f = nb * 16 + nt * 8 + (l >> 2);
        int k = 2 * (ks * 8 + (l & 3) + 4 * r);
        smu[S_W2X + idx] = f2h2(W2x[k * FDIM + f], W2x[(k + 1) * FDIM + f]);
    }
    if (t < HID) {
        sm[S_B1X + t]  = b1x[t];
        sm[S_B1P + t]  = b1p[t];
        sm[S_W1XL + t] = W1x[HID * HID + t];
        sm[S_W1PL + t] = W1p[HID * HID + t];
        sm[S_W2P + t]  = W2p[t];
    }
    if (t < FDIM) sm[S_B2X + t] = b2x[t];
    const float b2p0 = __ldg(b2p);
    __syncthreads();

    const int ntiles = (E + MT - 1) / MT;
    const int e  = t & 63;          // local edge
    const int kb = t >> 6;          // k-block 0..7 (16 feats = 8 pairs)
    const int esw = (e & 7) << 2;   // A-tile XOR swizzle (pair-index space)

    for (int tile = blockIdx.x; tile < ntiles; tile += NGRID) {
        // ---------------- gather ----------------
        const int ge = tile * MT + e;

        if (kb == 0) {
            if (ge < E) {
                int r = ei[ge], c = ei[E + ge];
                float rx = __ldg(pos + (size_t)r * 3 + 0) - __ldg(pos + (size_t)c * 3 + 0);
                float ry = __ldg(pos + (size_t)r * 3 + 1) - __ldg(pos + (size_t)c * 3 + 1);
                float rz = __ldg(pos + (size_t)r * 3 + 2) - __ldg(pos + (size_t)c * 3 + 2);
                sm[S_REL + e] = rx; sm[S_REL + 64 + e] = ry; sm[S_REL + 128 + e] = rz;
                sm[S_DIST + e] = rx * rx + ry * ry + rz * rz;
                scol[e] = c;
            } else {
                sm[S_REL + e] = 0.f; sm[S_REL + 64 + e] = 0.f; sm[S_REL + 128 + e] = 0.f;
                sm[S_DIST + e] = 0.f;
                scol[e] = -1;
            }
        }
        {
            uint32_t* base = smu + S_A + e * 64;
            const int p0 = kb * 8;                 // pair offset
            if (ge < E) {
                const int node = ei[(kb < 4 ? 0 : E) + ge];
                const float4* src = (const float4*)(x + (size_t)node * 64 + (kb & 3) * 16);
                float4 v0 = __ldg(src + 0), v1 = __ldg(src + 1);
                float4 v2 = __ldg(src + 2), v3 = __ldg(src + 3);
                *(uint4*)(base + (p0 ^ esw)) =
                    make_uint4(f2h2(v0.x, v0.y), f2h2(v0.z, v0.w), f2h2(v1.x, v1.y), f2h2(v1.z, v1.w));
                *(uint4*)(base + ((p0 + 4) ^ esw)) =
                    make_uint4(f2h2(v2.x, v2.y), f2h2(v2.z, v2.w), f2h2(v3.x, v3.y), f2h2(v3.z, v3.w));
            } else {
                *(uint4*)(base + (p0 ^ esw))       = make_uint4(0, 0, 0, 0);
                *(uint4*)(base + ((p0 + 4) ^ esw)) = make_uint4(0, 0, 0, 0);
            }
        }
        __syncthreads();

        // ---------------- GEMM1: warp = (m-group, n-slice), both MLPs ----------------
        const int mg = wid & 3;    // 16-edge m-group
        const int ws = wid >> 2;   // 32-col n-slice (of both W1x and W1p)
        float acc[8][4];           // n-tiles 0-3: phi_x, 4-7: phi_p
        #pragma unroll
        for (int n = 0; n < 8; n++)
            #pragma unroll
            for (int c = 0; c < 4; c++) acc[n][c] = 0.f;
        {
            const uint32_t* Ap = smu + S_A + (mg * 16 + qr) * 64;
            const int wbase = S_W1C + ws * 4096 + lane * 4;
            const int qsw = qr << 2;
            #pragma unroll
            for (int ks = 0; ks < 8; ks++) {
                const int col  = (ks * 8 + qc) ^ qsw;
                const int col4 = col ^ 4;
                uint32_t a[4];
                a[0] = Ap[col];  a[1] = Ap[512 + col];
                a[2] = Ap[col4]; a[3] = Ap[512 + col4];
                uint4 b0 = *(const uint4*)(smu + wbase + ks * 512);
                uint4 b1 = *(const uint4*)(smu + wbase + ks * 512 + 128);
                uint4 b2 = *(const uint4*)(smu + wbase + ks * 512 + 256);
                uint4 b3 = *(const uint4*)(smu + wbase + ks * 512 + 384);
                mma16(acc[0], a, b0.x, b0.y); mma16(acc[1], a, b0.z, b0.w);
                mma16(acc[2], a, b1.x, b1.y); mma16(acc[3], a, b1.z, b1.w);
                mma16(acc[4], a, b2.x, b2.y); mma16(acc[5], a, b2.z, b2.w);
                mma16(acc[6], a, b3.x, b3.y); mma16(acc[7], a, b3.z, b3.w);
            }
        }
        __syncthreads();   // all A-tile reads done before h overwrites it

        // ---------------- epilogue 1 (each warp: h slice + phi_p fold) ----------------
        {
            const float dd0 = sm[S_DIST + mg * 16 + qr];
            const float dd1 = sm[S_DIST + mg * 16 + qr + 8];
            const int sw = qr << 2;
            const int r0 = mg * 16 + qr;
            // phi_x: h = silu(acc + b1x + dist*w1xL) -> S_A (half2, swizzled)
            #pragma unroll
            for (int nt = 0; nt < 4; nt++) {
                const int j0 = ws * 32 + nt * 8 + 2 * qc;
                const int pj = ws * 16 + nt * 4 + qc;       // pair index of (j0, j0+1)
                const float bj0 = sm[S_B1X + j0],  bj1 = sm[S_B1X + j0 + 1];
                const float lj0 = sm[S_W1XL + j0], lj1 = sm[S_W1XL + j0 + 1];
                float h00 = silu_f(acc[nt][0] + bj0 + dd0 * lj0);
                float h01 = silu_f(acc[nt][1] + bj1 + dd0 * lj1);
                float h10 = silu_f(acc[nt][2] + bj0 + dd1 * lj0);
                float h11 = silu_f(acc[nt][3] + bj1 + dd1 * lj1);
                smu[S_A + r0 * 64 + (pj ^ sw)]       = f2h2(h00, h01);
                smu[S_A + (r0 + 8) * 64 + (pj ^ sw)] = f2h2(h10, h11);
            }
            // phi_p: fold to per-edge partial over this 32-col slice
            float pr0 = 0.f, pr1 = 0.f;
            #pragma unroll
            for (int nt = 0; nt < 4; nt++) {
                const int j0 = ws * 32 + nt * 8 + 2 * qc;
                const float bj0 = sm[S_B1P + j0],  bj1 = sm[S_B1P + j0 + 1];
                const float lj0 = sm[S_W1PL + j0], lj1 = sm[S_W1PL + j0 + 1];
                const float w0  = sm[S_W2P + j0],  w1  = sm[S_W2P + j0 + 1];
                pr0 += silu_f(acc[4 + nt][0] + bj0 + dd0 * lj0) * w0
                     + silu_f(acc[4 + nt][1] + bj1 + dd0 * lj1) * w1;
                pr1 += silu_f(acc[4 + nt][2] + bj0 + dd1 * lj0) * w0
                     + silu_f(acc[4 + nt][3] + bj1 + dd1 * lj1) * w1;
            }
            pr0 += __shfl_xor_sync(0xffffffff, pr0, 1);
            pr0 += __shfl_xor_sync(0xffffffff, pr0, 2);
            pr1 += __shfl_xor_sync(0xffffffff, pr1, 1);
            pr1 += __shfl_xor_sync(0xffffffff, pr1, 2);
            if (qc == 0) {
                sm[S_WACC + ws * 64 + r0]     = pr0;
                sm[S_WACC + ws * 64 + r0 + 8] = pr1;
            }
        }
        __syncthreads();

        // ---------------- pos scatter ----------------
        if (t < 64) {
            const int c = scol[t];
            if (c >= 0) {
                float w = b2p0 + sm[S_WACC + t] + sm[S_WACC + 64 + t]
                               + sm[S_WACC + 128 + t] + sm[S_WACC + 192 + t];
                float px = w * sm[S_REL + t];
                float py = w * sm[S_REL + 64 + t];
                float pz = w * sm[S_REL + 128 + t];
                float* dp = out_pos + (size_t)c * 3;
                asm volatile("red.global.add.f32 [%0], %1;" :: "l"(dp + 0), "f"(px) : "memory");
                asm volatile("red.global.add.f32 [%0], %1;" :: "l"(dp + 1), "f"(py) : "memory");
                asm volatile("red.global.add.f32 [%0], %1;" :: "l"(dp + 2), "f"(pz) : "memory");
            }
        }

        // ---------------- GEMM2: h @ W2x ----------------
        {
            const int m2  = wid & 3;     // 16-edge m-tile
            const int nb2 = wid >> 2;    // 16-col n-slice
            float acc2[2][4];
            #pragma unroll
            for (int n = 0; n < 2; n++)
                #pragma unroll
                for (int c = 0; c < 4; c++) acc2[n][c] = 0.f;

            const int wbase = S_W2X + nb2 * 1024 + lane * 4;
            const int qsw = qr << 2;
            const uint32_t* Ap = smu + S_A + (m2 * 16 + qr) * 64;
            #pragma unroll
            for (int ks = 0; ks < 8; ks++) {
                const int col  = (ks * 8 + qc) ^ qsw;
                const int col4 = col ^ 4;
                uint32_t a[4];
                a[0] = Ap[col];  a[1] = Ap[512 + col];
                a[2] = Ap[col4]; a[3] = Ap[512 + col4];
                uint4 bb = *(const uint4*)(smu + wbase + ks * 128);
                mma16(acc2[0], a, bb.x, bb.y);
                mma16(acc2[1], a, bb.z, bb.w);
            }

            // epilogue 2: + b2x, vectorized scatter-add
            const int r0 = m2 * 16 + qr;
            const int c0 = scol[r0];
            const int c1 = scol[r0 + 8];
            #pragma unroll
            for (int n = 0; n < 2; n++) {
                const int f0 = nb2 * 16 + n * 8 + 2 * qc;
                const float b20 = sm[S_B2X + f0], b21 = sm[S_B2X + f0 + 1];
                if (c0 >= 0) {
                    float v0 = acc2[n][0] + b20, v1 = acc2[n][1] + b21;
                    asm volatile("red.global.add.v2.f32 [%0], {%1, %2};"
                                 :: "l"(out_x + (size_t)c0 * 64 + f0), "f"(v0), "f"(v1) : "memory");
                }
                if (c1 >= 0) {
                    float v0 = acc2[n][2] + b20, v1 = acc2[n][3] + b21;
                    asm volatile("red.global.add.v2.f32 [%0], {%1, %2};"
                                 :: "l"(out_x + (size_t)c1 * 64 + f0), "f"(v0), "f"(v1) : "memory");
                }
            }
        }
        __syncthreads();   // protect S_A / S_WACC / S_COL before next tile's gather
    }
}

extern "C" void kernel_launch(void* const* d_in, const int* in_sizes, int n_in,
                              void* d_out, int out_size) {
    const float* x   = (const float*)d_in[0];
    const float* pos = (const float*)d_in[1];
    const int*   ei  = (const int*)d_in[2];
    const float* W1x = (const float*)d_in[3];
    const float* b1x = (const float*)d_in[4];
    const float* W2x = (const float*)d_in[5];
    const float* b2x = (const float*)d_in[6];
    const float* W1p = (const float*)d_in[7];
    const float* b1p = (const float*)d_in[8];
    const float* W2p = (const float*)d_in[9];
    const float* b2p = (const float*)d_in[10];

    const int N = in_sizes[0] / FDIM;
    const int E = in_sizes[2] / 2;

    float* out     = (float*)d_out;
    float* out_x   = out;
    float* out_pos = out + (size_t)N * FDIM;

    cudaMemsetAsync(d_out, 0, (size_t)out_size * sizeof(float), 0);

    cudaFuncSetAttribute(emp_mma_kernel,
                         cudaFuncAttributeMaxDynamicSharedMemorySize, SMEM_BYTES);

    emp_mma_kernel<<<NGRID, NTHR, SMEM_BYTES>>>(
        x, pos, ei, W1x, b1x, W2x, b2x, W1p, b1p, W2p, b2p, out_x, out_pos, E);
}

// round 16
// speedup vs baseline: 2.1683x; 1.0976x over previous
#include <cuda_runtime.h>
#include <cuda_fp16.h>
#include <cstdint>

#define NTHR  512
#define NGRID 148
#define MT    64          // edges per tile
#define FDIM  64
#define HID   128

// ---- smem layout (uint32/float offsets), all dense ----
#define S_A    0            // 64 x 64 uint32 (half2 pairs), XOR-swizzled, reused as h
#define S_W1C  4096         // [ws4][ks8][grp4][lane32][4] = 16384 uint32 (W1x+W1p halves)
#define S_W2X  20480        // [nb4][ks8][lane32][4] = 4096 uint32
#define S_B1X  24576        // 128 fp32
#define S_B1P  24704
#define S_W1XL 24832        // dist^2 row of W1x
#define S_W1PL 24960
#define S_W2P  25088        // 128 fp32
#define S_B2X  25216        // 64
#define S_DIST 25280        // 64
#define S_REL  25344        // 3 x 64
#define S_WACC 25536        // 4 x 64
#define S_COL  25792        // 64 (int)
#define S_STG  25856        // 64 x 132 fp32 staging (cp.async dst)
#define S_TOT  34304
#define SMEM_BYTES (S_TOT * 4)

__device__ __forceinline__ uint32_t f2h2(float lo, float hi) {
    __half2 h = __floats2half2_rn(lo, hi);
    return *(uint32_t*)&h;
}
static __device__ __forceinline__ float silu_f(float v) {
    return v * (1.0f / (1.0f + __expf(-v)));
}
__device__ __forceinline__ void mma16(float* c, const uint32_t* a, uint32_t b0, uint32_t b1) {
    asm volatile("mma.sync.aligned.m16n8k16.row.col.f32.f16.f16.f32 "
        "{%0,%1,%2,%3}, {%4,%5,%6,%7}, {%8,%9}, {%0,%1,%2,%3};"
        : "+f"(c[0]), "+f"(c[1]), "+f"(c[2]), "+f"(c[3])
        : "r"(a[0]), "r"(a[1]), "r"(a[2]), "r"(a[3]), "r"(b0), "r"(b1));
}
__device__ __forceinline__ void cpasync16(uint32_t dst, const void* src) {
    asm volatile("cp.async.ca.shared.global [%0], [%1], 16;" :: "r"(dst), "l"(src) : "memory");
}
#define CP_COMMIT() asm volatile("cp.async.commit_group;" ::: "memory")
#define CP_WAIT0()  asm volatile("cp.async.wait_group 0;" ::: "memory")

extern "C" __global__ void __launch_bounds__(NTHR, 1)
emp_mma_kernel(const float* __restrict__ x,
               const float* __restrict__ pos,
               const int* __restrict__ ei,
               const float* __restrict__ W1x, const float* __restrict__ b1x,
               const float* __restrict__ W2x, const float* __restrict__ b2x,
               const float* __restrict__ W1p, const float* __restrict__ b1p,
               const float* __restrict__ W2p, const float* __restrict__ b2p,
               float* __restrict__ out_x, float* __restrict__ out_pos,
               int E)
{
    extern __shared__ float sm[];
    uint32_t* smu = (uint32_t*)sm;
    int* scol = (int*)(sm + S_COL);

    const int t = threadIdx.x;
    const int lane = t & 31, wid = t >> 5;
    const int qr = lane >> 2, qc = lane & 3;

    uint32_t sb;
    asm("{ .reg .u64 tt; cvta.to.shared.u64 tt, %1; cvt.u32.u64 %0, tt; }"
        : "=r"(sb) : "l"(sm));

    // ---- one-time weight staging into m16n8k16 fragment layout (half2 packed) ----
    for (int idx = t; idx < 16384; idx += NTHR) {
        int q = idx & 3, l = (idx >> 2) & 31, grp = (idx >> 7) & 3,
            ks = (idx >> 9) & 7, ws = (idx >> 12) & 3;
        int nt = grp * 2 + (q >> 1), r = q & 1;
        int n = ws * 32 + (nt & 3) * 8 + (l >> 2);
        int k = 2 * (ks * 8 + (l & 3) + 4 * r);
        const float* W = (nt >= 4) ? W1p : W1x;
        smu[S_W1C + idx] = f2h2(W[k * HID + n], W[(k + 1) * HID + n]);
    }
    for (int idx = t; idx < 4096; idx += NTHR) {
        int q = idx & 3, l = (idx >> 2) & 31, ks = (idx >> 7) & 7, nb = (idx >> 10) & 3;
        int nt = q >> 1, r = q & 1;
        int f = nb * 16 + nt * 8 + (l >> 2);
        int k = 2 * (ks * 8 + (l & 3) + 4 * r);
        smu[S_W2X + idx] = f2h2(W2x[k * FDIM + f], W2x[(k + 1) * FDIM + f]);
    }
    if (t < HID) {
        sm[S_B1X + t]  = b1x[t];
        sm[S_B1P + t]  = b1p[t];
        sm[S_W1XL + t] = W1x[HID * HID + t];
        sm[S_W1PL + t] = W1p[HID * HID + t];
        sm[S_W2P + t]  = W2p[t];
    }
    if (t < FDIM) sm[S_B2X + t] = b2x[t];
    const float b2p0 = __ldg(b2p);

    const int ntiles = (E + MT - 1) / MT;
    const int e2   = t & 63;        // local edge (gather/commit role)
    const int part = t >> 6;        // 0..7: 16-float chunk of [x_row|x_col]
    const int esw  = (e2 & 7) << 2; // A-tile XOR swizzle (pair-index space)
    const uint32_t stg_dst = sb + (uint32_t)(S_STG + e2 * 132 + part * 16) * 4u;

    // ---- prologue: prefetch tile0 into staging ----
    int cr = 0, cc = -1;           // current tile's (row, col) for part==0 threads
    {
        const int ge = blockIdx.x * MT + e2;
        int node = 0;
        if (ge < E) node = ei[(part < 4 ? 0 : E) + ge];
        if (part == 0) { cr = node; cc = (ge < E) ? ei[E + ge] : -1; }
        const float* src = x + (size_t)node * 64 + (part & 3) * 16;
        #pragma unroll
        for (int i = 0; i < 4; i++) cpasync16(stg_dst + i * 16, src + i * 4);
        CP_COMMIT();
    }
    __syncthreads();   // also covers weight staging

    for (int tile = blockIdx.x; tile < ntiles; tile += NGRID) {
        CP_WAIT0();
        __syncthreads();   // staging arrived everywhere; prev tile's S_A reads done

        // ---------------- commit: staging fp32 -> S_A fp16 swizzled ----------------
        const int ge = tile * MT + e2;
        {
            if (part == 0) {
                if (ge < E) {
                    float ax = __ldg(pos + (size_t)cr * 3 + 0) - __ldg(pos + (size_t)cc * 3 + 0);
                    float ay = __ldg(pos + (size_t)cr * 3 + 1) - __ldg(pos + (size_t)cc * 3 + 1);
                    float az = __ldg(pos + (size_t)cr * 3 + 2) - __ldg(pos + (size_t)cc * 3 + 2);
                    sm[S_REL + e2] = ax; sm[S_REL + 64 + e2] = ay; sm[S_REL + 128 + e2] = az;
                    sm[S_DIST + e2] = ax * ax + ay * ay + az * az;
                    scol[e2] = cc;
                } else {
                    sm[S_REL + e2] = 0.f; sm[S_REL + 64 + e2] = 0.f; sm[S_REL + 128 + e2] = 0.f;
                    sm[S_DIST + e2] = 0.f;
                    scol[e2] = -1;
                }
            }
            uint32_t* base = smu + S_A + e2 * 64;
            const int p0 = part * 8;   // pair offset
            if (ge < E) {
                const float4* sp = (const float4*)(sm + S_STG + e2 * 132 + part * 16);
                float4 v0 = sp[0], v1 = sp[1], v2 = sp[2], v3 = sp[3];
                *(uint4*)(base + (p0 ^ esw)) =
                    make_uint4(f2h2(v0.x, v0.y), f2h2(v0.z, v0.w), f2h2(v1.x, v1.y), f2h2(v1.z, v1.w));
                *(uint4*)(base + ((p0 + 4) ^ esw)) =
                    make_uint4(f2h2(v2.x, v2.y), f2h2(v2.z, v2.w), f2h2(v3.x, v3.y), f2h2(v3.z, v3.w));
            } else {
                *(uint4*)(base + (p0 ^ esw))       = make_uint4(0, 0, 0, 0);
                *(uint4*)(base + ((p0 + 4) ^ esw)) = make_uint4(0, 0, 0, 0);
            }
        }
        __syncthreads();

        // ---- prefetch next tile's edge indices (hidden under GEMM1) ----
        const int tile_n = tile + NGRID;
        int nnode = 0, ncol = -1;
        {
            const int geN = tile_n * MT + e2;
            const bool vn = (tile_n < ntiles) && (geN < E);
            if (vn) nnode = ei[(part < 4 ? 0 : E) + geN];
            if (part == 0) ncol = vn ? ei[E + geN] : -1;
        }

        // ---------------- GEMM1: warp = (m-group, n-slice), both MLPs ----------------
        const int mg = wid & 3;    // 16-edge m-group
        const int ws = wid >> 2;   // 32-col n-slice (of both W1x and W1p)
        float acc[8][4];           // n-tiles 0-3: phi_x, 4-7: phi_p
        #pragma unroll
        for (int n = 0; n < 8; n++)
            #pragma unroll
            for (int c = 0; c < 4; c++) acc[n][c] = 0.f;
        {
            const uint32_t* Ap = smu + S_A + (mg * 16 + qr) * 64;
            const int wbase = S_W1C + ws * 4096 + lane * 4;
            const int qsw = qr << 2;
            #pragma unroll
            for (int ks = 0; ks < 8; ks++) {
                const int col  = (ks * 8 + qc) ^ qsw;
                const int col4 = col ^ 4;
                uint32_t a[4];
                a[0] = Ap[col];  a[1] = Ap[512 + col];
                a[2] = Ap[col4]; a[3] = Ap[512 + col4];
                uint4 b0 = *(const uint4*)(smu + wbase + ks * 512);
                uint4 b1 = *(const uint4*)(smu + wbase + ks * 512 + 128);
                uint4 b2 = *(const uint4*)(smu + wbase + ks * 512 + 256);
                uint4 b3 = *(const uint4*)(smu + wbase + ks * 512 + 384);
                mma16(acc[0], a, b0.x, b0.y); mma16(acc[1], a, b0.z, b0.w);
                mma16(acc[2], a, b1.x, b1.y); mma16(acc[3], a, b1.z, b1.w);
                mma16(acc[4], a, b2.x, b2.y); mma16(acc[5], a, b2.z, b2.w);
                mma16(acc[6], a, b3.x, b3.y); mma16(acc[7], a, b3.z, b3.w);
            }
        }

        // ---- issue next tile's x-row cp.asyncs (hidden under epilogue+GEMM2) ----
        if (tile_n < ntiles) {
            const float* srcN = x + (size_t)nnode * 64 + (part & 3) * 16;
            #pragma unroll
            for (int i = 0; i < 4; i++) cpasync16(stg_dst + i * 16, srcN + i * 4);
        }
        CP_COMMIT();

        __syncthreads();   // all A-tile reads done before h overwrites it

        // ---------------- epilogue 1 (each warp: h slice + phi_p fold) ----------------
        {
            const float dd0 = sm[S_DIST + mg * 16 + qr];
            const float dd1 = sm[S_DIST + mg * 16 + qr + 8];
            const int sw = qr << 2;
            const int r0 = mg * 16 + qr;
            #pragma unroll
            for (int nt = 0; nt < 4; nt++) {
                const int j0 = ws * 32 + nt * 8 + 2 * qc;
                const int pj = ws * 16 + nt * 4 + qc;
                const float bj0 = sm[S_B1X + j0],  bj1 = sm[S_B1X + j0 + 1];
                const float lj0 = sm[S_W1XL + j0], lj1 = sm[S_W1XL + j0 + 1];
                float h00 = silu_f(acc[nt][0] + bj0 + dd0 * lj0);
                float h01 = silu_f(acc[nt][1] + bj1 + dd0 * lj1);
                float h10 = silu_f(acc[nt][2] + bj0 + dd1 * lj0);
                float h11 = silu_f(acc[nt][3] + bj1 + dd1 * lj1);
                smu[S_A + r0 * 64 + (pj ^ sw)]       = f2h2(h00, h01);
                smu[S_A + (r0 + 8) * 64 + (pj ^ sw)] = f2h2(h10, h11);
            }
            float pr0 = 0.f, pr1 = 0.f;
            #pragma unroll
            for (int nt = 0; nt < 4; nt++) {
                const int j0 = ws * 32 + nt * 8 + 2 * qc;
                const float bj0 = sm[S_B1P + j0],  bj1 = sm[S_B1P + j0 + 1];
                const float lj0 = sm[S_W1PL + j0], lj1 = sm[S_W1PL + j0 + 1];
                const float w0  = sm[S_W2P + j0],  w1  = sm[S_W2P + j0 + 1];
                pr0 += silu_f(acc[4 + nt][0] + bj0 + dd0 * lj0) * w0
                     + silu_f(acc[4 + nt][1] + bj1 + dd0 * lj1) * w1;
                pr1 += silu_f(acc[4 + nt][2] + bj0 + dd1 * lj0) * w0
                     + silu_f(acc[4 + nt][3] + bj1 + dd1 * lj1) * w1;
            }
            pr0 += __shfl_xor_sync(0xffffffff, pr0, 1);
            pr0 += __shfl_xor_sync(0xffffffff, pr0, 2);
            pr1 += __shfl_xor_sync(0xffffffff, pr1, 1);
            pr1 += __shfl_xor_sync(0xffffffff, pr1, 2);
            if (qc == 0) {
                sm[S_WACC + ws * 64 + r0]     = pr0;
                sm[S_WACC + ws * 64 + r0 + 8] = pr1;
            }
        }
        __syncthreads();

        // ---------------- pos scatter ----------------
        if (t < 64) {
            const int c = scol[t];
            if (c >= 0) {
                float w = b2p0 + sm[S_WACC + t] + sm[S_WACC + 64 + t]
                               + sm[S_WACC + 128 + t] + sm[S_WACC + 192 + t];
                float px = w * sm[S_REL + t];
                float py = w * sm[S_REL + 64 + t];
                float pz = w * sm[S_REL + 128 + t];
                float* dp = out_pos + (size_t)c * 3;
                asm volatile("red.global.add.f32 [%0], %1;" :: "l"(dp + 0), "f"(px) : "memory");
                asm volatile("red.global.add.f32 [%0], %1;" :: "l"(dp + 1), "f"(py) : "memory");
                asm volatile("red.global.add.f32 [%0], %1;" :: "l"(dp + 2), "f"(pz) : "memory");
            }
        }

        // ---------------- GEMM2: h @ W2x ----------------
        {
            const int m2  = wid & 3;
            const int nb2 = wid >> 2;
            float acc2[2][4];
            #pragma unroll
            for (int n = 0; n < 2; n++)
                #pragma unroll
                for (int c = 0; c < 4; c++) acc2[n][c] = 0.f;

            const int wbase = S_W2X + nb2 * 1024 + lane * 4;
            const int qsw = qr << 2;
            const uint32_t* Ap = smu + S_A + (m2 * 16 + qr) * 64;
            #pragma unroll
            for (int ks = 0; ks < 8; ks++) {
                const int col  = (ks * 8 + qc) ^ qsw;
                const int col4 = col ^ 4;
                uint32_t a[4];
                a[0] = Ap[col];  a[1] = Ap[512 + col];
                a[2] = Ap[col4]; a[3] = Ap[512 + col4];
                uint4 bb = *(const uint4*)(smu + wbase + ks * 128);
                mma16(acc2[0], a, bb.x, bb.y);
                mma16(acc2[1], a, bb.z, bb.w);
            }

            const int r0 = m2 * 16 + qr;
            const int c0 = scol[r0];
            const int c1 = scol[r0 + 8];
            #pragma unroll
            for (int n = 0; n < 2; n++) {
                const int f0 = nb2 * 16 + n * 8 + 2 * qc;
                const float b20 = sm[S_B2X + f0], b21 = sm[S_B2X + f0 + 1];
                if (c0 >= 0) {
                    float v0 = acc2[n][0] + b20, v1 = acc2[n][1] + b21;
                    asm volatile("red.global.add.v2.f32 [%0], {%1, %2};"
                                 :: "l"(out_x + (size_t)c0 * 64 + f0), "f"(v0), "f"(v1) : "memory");
                }
                if (c1 >= 0) {
                    float v0 = acc2[n][2] + b20, v1 = acc2[n][3] + b21;
                    asm volatile("red.global.add.v2.f32 [%0], {%1, %2};"
                                 :: "l"(out_x + (size_t)c1 * 64 + f0), "f"(v0), "f"(v1) : "memory");
                }
            }
        }

        cr = nnode; cc = ncol;
        // loop-top __syncthreads protects S_A / scol / staging
    }
}

extern "C" void kernel_launch(void* const* d_in, const int* in_sizes, int n_in,
                              void* d_out, int out_size) {
    const float* x   = (const float*)d_in[0];
    const float* pos = (const float*)d_in[1];
    const int*   ei  = (const int*)d_in[2];
    const float* W1x = (const float*)d_in[3];
    const float* b1x = (const float*)d_in[4];
    const float* W2x = (const float*)d_in[5];
    const float* b2x = (const float*)d_in[6];
    const float* W1p = (const float*)d_in[7];
    const float* b1p = (const float*)d_in[8];
    const float* W2p = (const float*)d_in[9];
    const float* b2p = (const float*)d_in[10];

    const int N = in_sizes[0] / FDIM;
    const int E = in_sizes[2] / 2;

    float* out     = (float*)d_out;
    float* out_x   = out;
    float* out_pos = out + (size_t)N * FDIM;

    cudaMemsetAsync(d_out, 0, (size_t)out_size * sizeof(float), 0);

    cudaFuncSetAttribute(emp_mma_kernel,
                         cudaFuncAttributeMaxDynamicSharedMemorySize, SMEM_BYTES);

    emp_mma_kernel<<<NGRID, NTHR, SMEM_BYTES>>>(
        x, pos, ei, W1x, b1x, W2x, b2x, W1p, b1p, W2p, b2p, out_x, out_pos, E);
}